// round 8
// baseline (speedup 1.0000x reference)
#include <cuda_runtime.h>
#include <math.h>
#include <stdint.h>

#define Nn 50000
#define Ee 640000
#define Dd 128
#define Hh 8
#define DHd 16
#define FFd 256
#define Cc 5
#define Ll 6
#define EPSf 1e-5f

#define SCAN_B 1024
#define SCAN_NB ((Nn + SCAN_B - 1) / SCAN_B)  // 49

// ---------------- scratch (device globals; no allocs allowed) ----------------
__device__ float g_q[Nn * Dd];
__device__ float g_k[Nn * Dd];
__device__ float g_v[Nn * Dd];
__device__ float g_attn[Nn * Dd];
__device__ float g_tmp1[Nn * Dd];
__device__ float g_tmp2[Nn * Dd];
__device__ float g_ff[Nn * FFd];
__device__ double g_sum1[Dd];
__device__ double g_sq1[Dd];
__device__ double g_sum2[Dd];
__device__ double g_sq2[Dd];
// CSR
__device__ int g_deg[Nn];
__device__ int g_cursor[Nn];
__device__ int g_rowptr[Nn + 1];
__device__ int g_scan[Nn];
__device__ int g_bsum[SCAN_NB];
__device__ int g_col[Ee];

// ---------------- tf32 helpers (baseline PTX, no sm_103a features) ----------------
__device__ __forceinline__ void tf32_split(float x, uint32_t& hi, uint32_t& lo) {
    uint32_t h;
    asm("cvt.rna.tf32.f32 %0, %1;" : "=r"(h) : "f"(x));
    float l = x - __uint_as_float(h);
    uint32_t lw;
    asm("cvt.rna.tf32.f32 %0, %1;" : "=r"(lw) : "f"(l));
    hi = h;
    lo = lw;
}

// D += A(16x8,row) * B(8x8,col), tf32 inputs, fp32 accum
__device__ __forceinline__ void mma8(float* c, const uint32_t* a, const uint32_t* b) {
    asm volatile(
        "mma.sync.aligned.m16n8k8.row.col.f32.tf32.tf32.f32 "
        "{%0,%1,%2,%3}, {%4,%5,%6,%7}, {%8,%9}, {%0,%1,%2,%3};"
        : "+f"(c[0]), "+f"(c[1]), "+f"(c[2]), "+f"(c[3])
        : "r"(a[0]), "r"(a[1]), "r"(a[2]), "r"(a[3]), "r"(b[0]), "r"(b[1]));
}

// ---------------- CSR build ----------------
__global__ void csr_zero_kernel() {
    int i = blockIdx.x * blockDim.x + threadIdx.x;
    if (i < Nn) {
        g_deg[i] = 0;
        g_cursor[i] = 0;
    }
}

__global__ void csr_hist_kernel(const int* __restrict__ ei) {
    int e = blockIdx.x * blockDim.x + threadIdx.x;
    if (e < Ee) atomicAdd(&g_deg[ei[Ee + e]], 1);
}

__global__ void csr_scan1_kernel() {
    __shared__ int sh[SCAN_B];
    int gi = blockIdx.x * SCAN_B + threadIdx.x;
    int v = (gi < Nn) ? g_deg[gi] : 0;
    sh[threadIdx.x] = v;
    __syncthreads();
#pragma unroll
    for (int off = 1; off < SCAN_B; off <<= 1) {
        int t = (threadIdx.x >= off) ? sh[threadIdx.x - off] : 0;
        __syncthreads();
        sh[threadIdx.x] += t;
        __syncthreads();
    }
    if (gi < Nn) g_scan[gi] = sh[threadIdx.x];
    if (threadIdx.x == SCAN_B - 1) g_bsum[blockIdx.x] = sh[threadIdx.x];
}

__global__ void csr_scan23_kernel() {
    __shared__ int soff;
    if (threadIdx.x == 0) {
        int acc = 0;
        for (int i = 0; i < (int)blockIdx.x; i++) acc += g_bsum[i];
        soff = acc;
    }
    __syncthreads();
    int gi = blockIdx.x * SCAN_B + threadIdx.x;
    if (gi < Nn) g_rowptr[gi + 1] = g_scan[gi] + soff;
    if (gi == 0) g_rowptr[0] = 0;
}

__global__ void csr_scatter_kernel(const int* __restrict__ ei) {
    int e = blockIdx.x * blockDim.x + threadIdx.x;
    if (e >= Ee) return;
    int src = ei[e], dst = ei[Ee + e];
    int pos = g_rowptr[dst] + atomicAdd(&g_cursor[dst], 1);
    g_col[pos] = src;
}

__global__ void zero_stats_kernel(double* __restrict__ a, double* __restrict__ b) {
    int t = threadIdx.x;
    if (t < Dd) {
        a[t] = 0.0;
        b[t] = 0.0;
    }
}

// ---------------- warp-mma tf32 split-2 fused GEMM ----------------
// C[M,NC] = op(A)[M,K] @ B[K,NC] (+bias)(+op(res))(relu). CTA tile 128x128,
// 8 warps (4 in M x 2 in N), warp tile 32x64. KC=16 chunks.
// BNA: BN applied to A input; BNRES: BN applied to residual; STATS: col sum/sq.
template <int K, int NC, bool BIAS, bool RELU, bool RES, bool BNA, bool BNRES,
          bool STATS, int NMAT>
__global__ __launch_bounds__(256, 2) void wm_gemm_kernel(
    const float* __restrict__ A,
    const float* __restrict__ B0, const float* __restrict__ B1, const float* __restrict__ B2,
    const float* __restrict__ bias, const float* __restrict__ res,
    const float* __restrict__ bng, const float* __restrict__ bnb,
    const double* __restrict__ bnsum, const double* __restrict__ bnsq,
    double* __restrict__ stsum, double* __restrict__ stsq,
    float* __restrict__ C0, float* __restrict__ C1, float* __restrict__ C2) {
    const int KC = 16;
    const int NCH = K / KC;
    const int YPM = NC / 128;
    constexpr int PSZ = BNA ? K : (BNRES ? 128 : 1);
    constexpr int SSZ = STATS ? 128 : 1;
    const int AP = 20;    // A smem pitch [m][k]
    const int BP = 136;   // B smem pitch [k][n]

    __shared__ uint32_t Ah[128 * AP], Al[128 * AP];
    __shared__ uint32_t Bh[KC * BP], Bl[KC * BP];
    __shared__ float s_sc[PSZ], s_sh[PSZ];
    __shared__ float s_cs[SSZ], s_cq[SSZ];

    int tid = threadIdx.x;
    int lane = tid & 31;
    int wid = tid >> 5;
    int wm = wid >> 1;            // 0..3
    int wn = wid & 1;             // 0..1
    int lr = lane >> 2;           // 0..7
    int lc = lane & 3;            // 0..3
    int rowBase = blockIdx.x * 128;
    int mat = (NMAT > 1) ? ((int)blockIdx.y / YPM) : 0;
    int colBase = ((int)blockIdx.y % YPM) * 128;
    const float* B = (NMAT > 1) ? (mat == 0 ? B0 : (mat == 1 ? B1 : B2)) : B0;
    float* C = (NMAT > 1) ? (mat == 0 ? C0 : (mat == 1 ? C1 : C2)) : C0;

    if (BNA || BNRES) {
        for (int c = tid; c < PSZ; c += 256) {
            double m = bnsum[c] / (double)Nn;
            double var = bnsq[c] / (double)Nn - m * m;
            float sc = rsqrtf((float)var + EPSf) * bng[c];
            s_sc[c] = sc;
            s_sh[c] = bnb[c] - (float)m * sc;
        }
        __syncthreads();
    }
    if (STATS) {
        if (tid < SSZ) {
            s_cs[tid] = 0.f;
            s_cq[tid] = 0.f;
        }
    }

    float acc[2][8][4];
#pragma unroll
    for (int i = 0; i < 2; i++)
#pragma unroll
        for (int j = 0; j < 8; j++)
#pragma unroll
            for (int t = 0; t < 4; t++) acc[i][j][t] = 0.f;

    // per-thread load coords
    const int ar = tid >> 2;          // A row 0..63 (l adds 64)
    const int ac = (tid & 3) * 4;     // A col 0,4,8,12
    const int br = tid >> 5;          // B row 0..7 (l adds 8)
    const int bc = (tid & 31) * 4;    // B col 0..124

    for (int ch = 0; ch < NCH; ch++) {
        int kt = ch * KC;
        if (ch > 0) __syncthreads();  // previous chunk fully consumed
        // ---- A chunk: 128 x 16, split hi/lo, [m][k] pitch 20 ----
#pragma unroll
        for (int l = 0; l < 2; l++) {
            int am = ar + l * 64;
            int grow = rowBase + am;
            float4 av = make_float4(0.f, 0.f, 0.f, 0.f);
            if (grow < Nn) av = *(const float4*)&A[(size_t)grow * K + kt + ac];
            if (BNA) {
                av.x = av.x * s_sc[kt + ac + 0] + s_sh[kt + ac + 0];
                av.y = av.y * s_sc[kt + ac + 1] + s_sh[kt + ac + 1];
                av.z = av.z * s_sc[kt + ac + 2] + s_sh[kt + ac + 2];
                av.w = av.w * s_sc[kt + ac + 3] + s_sh[kt + ac + 3];
            }
            uint4 h4, l4;
            tf32_split(av.x, h4.x, l4.x);
            tf32_split(av.y, h4.y, l4.y);
            tf32_split(av.z, h4.z, l4.z);
            tf32_split(av.w, h4.w, l4.w);
            *(uint4*)&Ah[am * AP + ac] = h4;
            *(uint4*)&Al[am * AP + ac] = l4;
        }
        // ---- B chunk: 16 x 128, split hi/lo, [k][n] pitch 136 ----
#pragma unroll
        for (int l = 0; l < 2; l++) {
            int bk = br + l * 8;
            float4 bv = *(const float4*)&B[(size_t)(kt + bk) * NC + colBase + bc];
            uint4 h4, l4;
            tf32_split(bv.x, h4.x, l4.x);
            tf32_split(bv.y, h4.y, l4.y);
            tf32_split(bv.z, h4.z, l4.z);
            tf32_split(bv.w, h4.w, l4.w);
            *(uint4*)&Bh[bk * BP + bc] = h4;
            *(uint4*)&Bl[bk * BP + bc] = l4;
        }
        __syncthreads();

        // ---- compute: 2 k8-steps ----
#pragma unroll
        for (int kk = 0; kk < KC; kk += 8) {
            uint32_t ah[2][4], al[2][4];
#pragma unroll
            for (int fm = 0; fm < 2; fm++) {
                int mb = wm * 32 + fm * 16;
                ah[fm][0] = Ah[(mb + lr) * AP + kk + lc];
                ah[fm][1] = Ah[(mb + lr + 8) * AP + kk + lc];
                ah[fm][2] = Ah[(mb + lr) * AP + kk + lc + 4];
                ah[fm][3] = Ah[(mb + lr + 8) * AP + kk + lc + 4];
                al[fm][0] = Al[(mb + lr) * AP + kk + lc];
                al[fm][1] = Al[(mb + lr + 8) * AP + kk + lc];
                al[fm][2] = Al[(mb + lr) * AP + kk + lc + 4];
                al[fm][3] = Al[(mb + lr + 8) * AP + kk + lc + 4];
            }
#pragma unroll
            for (int fn = 0; fn < 8; fn++) {
                int nb = wn * 64 + fn * 8;
                uint32_t bh[2], bl[2];
                bh[0] = Bh[(kk + lc) * BP + nb + lr];
                bh[1] = Bh[(kk + lc + 4) * BP + nb + lr];
                bl[0] = Bl[(kk + lc) * BP + nb + lr];
                bl[1] = Bl[(kk + lc + 4) * BP + nb + lr];
#pragma unroll
                for (int fm = 0; fm < 2; fm++) {
                    mma8(acc[fm][fn], ah[fm], bh);
                    mma8(acc[fm][fn], ah[fm], bl);
                    mma8(acc[fm][fn], al[fm], bh);
                }
            }
        }
    }

    // ---------------- epilogue ----------------
#pragma unroll
    for (int fm = 0; fm < 2; fm++) {
        int r0 = rowBase + wm * 32 + fm * 16 + lr;
        int r1 = r0 + 8;
        bool v0 = r0 < Nn, v1 = r1 < Nn;
#pragma unroll
        for (int fn = 0; fn < 8; fn++) {
            int cl = wn * 64 + fn * 8 + lc * 2;
            int gc = colBase + cl;
            float d0 = acc[fm][fn][0], d1 = acc[fm][fn][1];
            float d2 = acc[fm][fn][2], d3 = acc[fm][fn][3];
            if (BIAS) {
                float b0 = bias[gc], b1 = bias[gc + 1];
                d0 += b0; d1 += b1; d2 += b0; d3 += b1;
            }
            if (RES) {
                float sc0 = BNRES ? s_sc[cl] : 1.f, sh0 = BNRES ? s_sh[cl] : 0.f;
                float sc1 = BNRES ? s_sc[cl + 1] : 1.f, sh1 = BNRES ? s_sh[cl + 1] : 0.f;
                if (v0) {
                    float2 rv = *(const float2*)&res[(size_t)r0 * NC + gc];
                    d0 += rv.x * sc0 + sh0;
                    d1 += rv.y * sc1 + sh1;
                }
                if (v1) {
                    float2 rv = *(const float2*)&res[(size_t)r1 * NC + gc];
                    d2 += rv.x * sc0 + sh0;
                    d3 += rv.y * sc1 + sh1;
                }
            }
            if (RELU) {
                d0 = d0 > 0.f ? d0 : 0.f;
                d1 = d1 > 0.f ? d1 : 0.f;
                d2 = d2 > 0.f ? d2 : 0.f;
                d3 = d3 > 0.f ? d3 : 0.f;
            }
            if (STATS) {
                float e0 = v0 ? d0 : 0.f, e1 = v0 ? d1 : 0.f;
                float e2 = v1 ? d2 : 0.f, e3 = v1 ? d3 : 0.f;
                atomicAdd(&s_cs[cl], e0 + e2);
                atomicAdd(&s_cs[cl + 1], e1 + e3);
                atomicAdd(&s_cq[cl], e0 * e0 + e2 * e2);
                atomicAdd(&s_cq[cl + 1], e1 * e1 + e3 * e3);
            }
            if (v0) *(float2*)&C[(size_t)r0 * NC + gc] = make_float2(d0, d1);
            if (v1) *(float2*)&C[(size_t)r1 * NC + gc] = make_float2(d2, d3);
        }
    }

    if (STATS) {
        __syncthreads();
        if (tid < SSZ) {
            atomicAdd(&stsum[colBase + tid], (double)s_cs[tid]);
            atomicAdd(&stsq[colBase + tid], (double)s_cq[tid]);
        }
    }
}

// ---------------- fused edge attention: one warp per dst node ----------------
__global__ void attn_fused_kernel() {
    int warp = blockIdx.x * (blockDim.x >> 5) + (threadIdx.x >> 5);
    int lane = threadIdx.x & 31;
    if (warp >= Nn) return;
    int dst = warp;

    float4 q4 = *(const float4*)&g_q[dst * Dd + lane * 4];

    float m = -INFINITY;
    float l = 0.0f;
    float4 acc = make_float4(0.f, 0.f, 0.f, 0.f);

    int beg = g_rowptr[dst];
    int end = g_rowptr[dst + 1];
    for (int j = beg; j < end; j++) {
        int src = g_col[j];
        float4 k4 = *(const float4*)&g_k[src * Dd + lane * 4];
        float p = q4.x * k4.x + q4.y * k4.y + q4.z * k4.z + q4.w * k4.w;
        p += __shfl_xor_sync(0xffffffffu, p, 1);
        p += __shfl_xor_sync(0xffffffffu, p, 2);
        float s = p * 0.25f;

        float newm = fmaxf(m, s);
        float corr = __expf(m - newm);
        float pe = __expf(s - newm);
        float4 v4 = *(const float4*)&g_v[src * Dd + lane * 4];
        acc.x = acc.x * corr + pe * v4.x;
        acc.y = acc.y * corr + pe * v4.y;
        acc.z = acc.z * corr + pe * v4.z;
        acc.w = acc.w * corr + pe * v4.w;
        l = l * corr + pe;
        m = newm;
    }
    float inv = (l > 0.f) ? (1.0f / l) : 0.0f;
    acc.x *= inv; acc.y *= inv; acc.z *= inv; acc.w *= inv;
    *(float4*)&g_attn[dst * Dd + lane * 4] = acc;
}

// ---------------- final projection (with fused BN on input) ----------------
__global__ void proj_kernel(const float* __restrict__ Wp, const float* __restrict__ bp,
                            const float* __restrict__ bng, const float* __restrict__ bnb,
                            float* __restrict__ out) {
    int warp = blockIdx.x * (blockDim.x >> 5) + (threadIdx.x >> 5);
    int lane = threadIdx.x & 31;
    if (warp >= Nn) return;

    float sc[4], sh[4];
#pragma unroll
    for (int i = 0; i < 4; i++) {
        int c = lane + 32 * i;
        double m = g_sum2[c] / (double)Nn;
        double var = g_sq2[c] / (double)Nn - m * m;
        float s = rsqrtf((float)var + EPSf) * bng[c];
        sc[i] = s;
        sh[i] = bnb[c] - (float)m * s;
    }

    float acc[Cc] = {0.f, 0.f, 0.f, 0.f, 0.f};
#pragma unroll
    for (int i = 0; i < 4; i++) {
        int k = lane + 32 * i;
        float xv = g_tmp2[warp * Dd + k] * sc[i] + sh[i];
#pragma unroll
        for (int c = 0; c < Cc; c++) acc[c] += xv * Wp[k * Cc + c];
    }
#pragma unroll
    for (int c = 0; c < Cc; c++) {
#pragma unroll
        for (int o = 16; o > 0; o >>= 1) acc[c] += __shfl_down_sync(0xffffffffu, acc[c], o);
    }
    if (lane == 0) {
#pragma unroll
        for (int c = 0; c < Cc; c++) out[warp * Cc + c] = acc[c] + bp[c];
    }
}

// ---------------- launch ----------------
extern "C" void kernel_launch(void* const* d_in, const int* in_sizes, int n_in,
                              void* d_out, int out_size) {
    const float* x   = (const float*)d_in[0];
    const int*   ei  = (const int*)d_in[1];
    const float* Wq  = (const float*)d_in[2];
    const float* Wk  = (const float*)d_in[3];
    const float* Wv  = (const float*)d_in[4];
    const float* Wo  = (const float*)d_in[5];
    const float* g1  = (const float*)d_in[6];
    const float* bn1 = (const float*)d_in[7];
    const float* W1  = (const float*)d_in[8];
    const float* bf1 = (const float*)d_in[9];
    const float* W2  = (const float*)d_in[10];
    const float* bf2 = (const float*)d_in[11];
    const float* g2  = (const float*)d_in[12];
    const float* bn2 = (const float*)d_in[13];
    const float* Wp  = (const float*)d_in[14];
    const float* bp  = (const float*)d_in[15];
    float* out = (float*)d_out;

    float *pq, *pk, *pv, *pattn, *ptmp1, *ptmp2, *pff;
    double *psum1, *psq1, *psum2, *psq2;
    cudaGetSymbolAddress((void**)&pq, g_q);
    cudaGetSymbolAddress((void**)&pk, g_k);
    cudaGetSymbolAddress((void**)&pv, g_v);
    cudaGetSymbolAddress((void**)&pattn, g_attn);
    cudaGetSymbolAddress((void**)&ptmp1, g_tmp1);
    cudaGetSymbolAddress((void**)&ptmp2, g_tmp2);
    cudaGetSymbolAddress((void**)&pff, g_ff);
    cudaGetSymbolAddress((void**)&psum1, g_sum1);
    cudaGetSymbolAddress((void**)&psq1, g_sq1);
    cudaGetSymbolAddress((void**)&psum2, g_sum2);
    cudaGetSymbolAddress((void**)&psq2, g_sq2);

    const int gemmRows = (Nn + 127) / 128;  // 391
    const int edgeBlocks = (Ee + 255) / 256;
    const int nodeBlocks = (Nn + 255) / 256;
    const int warpBlocks = (Nn + 7) / 8;

    csr_zero_kernel<<<nodeBlocks, 256>>>();
    csr_hist_kernel<<<edgeBlocks, 256>>>(ei);
    csr_scan1_kernel<<<SCAN_NB, SCAN_B>>>();
    // #4: layer-0 QKV (profiled launch)
    wm_gemm_kernel<Dd, Dd, false, false, false, false, false, false, 3>
        <<<dim3(gemmRows, 3), 256>>>(x, Wq, Wk, Wv, nullptr, nullptr,
                                     nullptr, nullptr, nullptr, nullptr,
                                     nullptr, nullptr, pq, pk, pv);
    csr_scan23_kernel<<<SCAN_NB, SCAN_B>>>();
    csr_scatter_kernel<<<edgeBlocks, 256>>>(ei);

    for (int i = 0; i < Ll; i++) {
        const float* wq = Wq + (size_t)i * Dd * Dd;
        const float* wk = Wk + (size_t)i * Dd * Dd;
        const float* wv = Wv + (size_t)i * Dd * Dd;
        const float* wo = Wo + (size_t)i * Dd * Dd;
        const float* w1 = W1 + (size_t)i * Dd * FFd;
        const float* w2 = W2 + (size_t)i * FFd * Dd;

        if (i > 0) {
            wm_gemm_kernel<Dd, Dd, false, false, false, true, false, false, 3>
                <<<dim3(gemmRows, 3), 256>>>(
                    ptmp2, wq, wk, wv, nullptr, nullptr,
                    g2 + (i - 1) * Dd, bn2 + (i - 1) * Dd,
                    psum2, psq2, nullptr, nullptr, pq, pk, pv);
        }

        attn_fused_kernel<<<warpBlocks, 256>>>();

        zero_stats_kernel<<<1, 128>>>(psum1, psq1);

        if (i == 0) {
            wm_gemm_kernel<Dd, Dd, false, false, true, false, false, true, 1>
                <<<dim3(gemmRows, 1), 256>>>(
                    pattn, wo, nullptr, nullptr, nullptr, x,
                    nullptr, nullptr, nullptr, nullptr,
                    psum1, psq1, ptmp1, nullptr, nullptr);
        } else {
            wm_gemm_kernel<Dd, Dd, false, false, true, false, true, true, 1>
                <<<dim3(gemmRows, 1), 256>>>(
                    pattn, wo, nullptr, nullptr, nullptr, ptmp2,
                    g2 + (i - 1) * Dd, bn2 + (i - 1) * Dd,
                    psum2, psq2, psum1, psq1, ptmp1, nullptr, nullptr);
        }

        wm_gemm_kernel<Dd, FFd, true, true, false, true, false, false, 1>
            <<<dim3(gemmRows, 2), 256>>>(
                ptmp1, w1, nullptr, nullptr, bf1 + i * FFd, nullptr,
                g1 + i * Dd, bn1 + i * Dd,
                psum1, psq1, nullptr, nullptr, pff, nullptr, nullptr);

        zero_stats_kernel<<<1, 128>>>(psum2, psq2);

        wm_gemm_kernel<FFd, Dd, true, false, true, false, true, true, 1>
            <<<dim3(gemmRows, 1), 256>>>(
                pff, w2, nullptr, nullptr, bf2 + i * Dd, ptmp1,
                g1 + i * Dd, bn1 + i * Dd,
                psum1, psq1, psum2, psq2, ptmp2, nullptr, nullptr);
    }

    proj_kernel<<<warpBlocks, 256>>>(Wp, bp, g2 + (Ll - 1) * Dd, bn2 + (Ll - 1) * Dd, out);
}